// round 1
// baseline (speedup 1.0000x reference)
#include <cuda_runtime.h>

#define BATCH 8
#define SEQ   2048
#define EMB   1024
#define HEAD  64
#define NTOK  (BATCH*SEQ)   // 16384
#define LOG2E 1.4426950408889634f

// scratch for Q, K, V projections (4 MB each)
__device__ float g_Q[NTOK*HEAD];
__device__ float g_K[NTOK*HEAD];
__device__ float g_V[NTOK*HEAD];

// ---------------------------------------------------------------------------
// Kernel 1: QKV projection.  Out[m][n] = sum_k X[m][k] * W[k][n]
// M=16384, N=64(=HEAD), K=1024.  Block tile 128x64, thread micro-tile 8x4.
// gridDim = (3, 128): x selects {Wq,Wk,Wv} -> {g_Q,g_K,g_V}
// ---------------------------------------------------------------------------
__global__ __launch_bounds__(256, 2) void qkv_kernel(
    const float* __restrict__ X,
    const float* __restrict__ Wq,
    const float* __restrict__ Wk,
    const float* __restrict__ Wv)
{
    __shared__ float Xs[128*32];   // [m][k] natural, pitch 32
    __shared__ float Ws[32*64];    // [k][n] natural, pitch 64

    const int tid = threadIdx.x;
    const int tx = tid & 15;       // n dimension (4 cols each)
    const int ty = tid >> 4;       // m dimension (8 rows each)

    const float* W;
    float* Out;
    if (blockIdx.x == 0)      { W = Wq; Out = g_Q; }
    else if (blockIdx.x == 1) { W = Wk; Out = g_K; }
    else                      { W = Wv; Out = g_V; }
    const int m0 = blockIdx.y * 128;

    float acc[8][4];
    #pragma unroll
    for (int i = 0; i < 8; i++)
        #pragma unroll
        for (int j = 0; j < 4; j++) acc[i][j] = 0.f;

    for (int kt = 0; kt < EMB; kt += 32) {
        // load X tile 128x32: 1024 float4, 4 per thread (coalesced)
        #pragma unroll
        for (int it = 0; it < 4; it++) {
            int f = tid + it * 256;
            int c = f & 7, r = f >> 3;
            *(float4*)&Xs[r*32 + 4*c] =
                *(const float4*)&X[(size_t)(m0 + r) * EMB + kt + 4*c];
        }
        // load W tile 32x64: 512 float4, 2 per thread (coalesced)
        #pragma unroll
        for (int it = 0; it < 2; it++) {
            int f = tid + it * 256;
            int c = f & 15, r = f >> 4;
            *(float4*)&Ws[r*64 + 4*c] =
                *(const float4*)&W[(size_t)(kt + r) * HEAD + 4*c];
        }
        __syncthreads();

        #pragma unroll
        for (int ch = 0; ch < 8; ch++) {   // 8 chunks of 4 k-values
            float4 xf[8];
            #pragma unroll
            for (int i = 0; i < 8; i++)
                xf[i] = *(float4*)&Xs[(8*ty + i)*32 + ch*4];
            float4 w0 = *(float4*)&Ws[(ch*4 + 0)*64 + 4*tx];
            float4 w1 = *(float4*)&Ws[(ch*4 + 1)*64 + 4*tx];
            float4 w2 = *(float4*)&Ws[(ch*4 + 2)*64 + 4*tx];
            float4 w3 = *(float4*)&Ws[(ch*4 + 3)*64 + 4*tx];
            #pragma unroll
            for (int i = 0; i < 8; i++) {
                float4 x = xf[i];
                acc[i][0] += x.x*w0.x + x.y*w1.x + x.z*w2.x + x.w*w3.x;
                acc[i][1] += x.x*w0.y + x.y*w1.y + x.z*w2.y + x.w*w3.y;
                acc[i][2] += x.x*w0.z + x.y*w1.z + x.z*w2.z + x.w*w3.z;
                acc[i][3] += x.x*w0.w + x.y*w1.w + x.z*w2.w + x.w*w3.w;
            }
        }
        __syncthreads();
    }

    #pragma unroll
    for (int i = 0; i < 8; i++) {
        float4 o = make_float4(acc[i][0], acc[i][1], acc[i][2], acc[i][3]);
        *(float4*)&Out[(size_t)(m0 + 8*ty + i) * HEAD + 4*tx] = o;
    }
}

// ---------------------------------------------------------------------------
// Kernel 2: flash attention.  64 queries x 128 keys per tile, online softmax.
// grid = (32, 8) = (q-tiles, batch), 256 threads.
// Thread layout: tx = tid&15 (8 key-cols each for S / 4 head-cols for O),
//                ty = tid>>4 (4 query-rows each).
// Shared (dynamic, 80 KB): Qs[64][64] | Ks[128][64] (XOR-swizzled 16B chunks,
//                          aliased with Ps[64][128]) | Vs[128][64]
// ---------------------------------------------------------------------------
__global__ __launch_bounds__(256, 2) void attn_kernel(float* __restrict__ out)
{
    extern __shared__ float smem[];
    float* Qs = smem;            // 4096 floats
    float* Ks = smem + 4096;     // 8192 floats (aliased with Ps)
    float* Vs = smem + 12288;    // 8192 floats
    float* Ps = Ks;              // P[64][128], pitch 128 -> exactly 8192 floats

    const int tid = threadIdx.x;
    const int tx = tid & 15;
    const int ty = tid >> 4;
    const int qb = blockIdx.x;   // 0..31
    const int b  = blockIdx.y;   // 0..7
    const int q0 = qb * 64;

    const float* Qg = g_Q + (size_t)b * SEQ * HEAD;
    const float* Kg = g_K + (size_t)b * SEQ * HEAD;
    const float* Vg = g_V + (size_t)b * SEQ * HEAD;

    // load Q tile 64x64 (natural layout; fragment reads are warp-broadcast)
    #pragma unroll
    for (int it = 0; it < 4; it++) {
        int f = tid + it * 256;
        int c = f & 15, r = f >> 4;
        *(float4*)&Qs[r*64 + 4*c] =
            *(const float4*)&Qg[(size_t)(q0 + r) * HEAD + 4*c];
    }

    float m_st[4], l_st[4], o[4][4];
    #pragma unroll
    for (int i = 0; i < 4; i++) {
        m_st[i] = -1e30f; l_st[i] = 0.f;
        #pragma unroll
        for (int j = 0; j < 4; j++) o[i][j] = 0.f;
    }

    const int ntiles = q0 / 128 + 1;
    const float sscale = 0.03125f * LOG2E;   // C^-0.5 * log2(e)

    for (int kt = 0; kt < ntiles; kt++) {
        const int k0 = kt * 128;
        __syncthreads();   // prior PV done reading Ps (alias of Ks); Q visible

        // load K (swizzled) and V (natural) tiles, 128x64 each, 8 f4/thread
        #pragma unroll
        for (int it = 0; it < 8; it++) {
            int f = tid + it * 256;
            int c = f & 15, r = f >> 4;
            float4 kv = *(const float4*)&Kg[(size_t)(k0 + r) * HEAD + 4*c];
            int cs = c ^ ((r >> 3) & 15);          // 16B-chunk XOR swizzle
            *(float4*)&Ks[r*64 + 4*cs] = kv;
            float4 vv = *(const float4*)&Vg[(size_t)(k0 + r) * HEAD + 4*c];
            *(float4*)&Vs[r*64 + 4*c] = vv;
        }
        __syncthreads();

        // ----- S = Q K^T (raw), acc[4 q][8 k] -----
        float acc[4][8];
        #pragma unroll
        for (int i = 0; i < 4; i++)
            #pragma unroll
            for (int j = 0; j < 8; j++) acc[i][j] = 0.f;

        #pragma unroll
        for (int ch = 0; ch < 16; ch++) {
            float4 qf[4];
            #pragma unroll
            for (int i = 0; i < 4; i++)
                qf[i] = *(float4*)&Qs[(4*ty + i)*64 + ch*4];
            #pragma unroll
            for (int j = 0; j < 8; j++) {
                // row 8*tx+j -> stored swizzle key is tx; read chunk = ch^tx
                float4 kf = *(float4*)&Ks[(8*tx + j)*64 + ((ch ^ tx) & 15)*4];
                #pragma unroll
                for (int i = 0; i < 4; i++) {
                    acc[i][j] += qf[i].x*kf.x + qf[i].y*kf.y
                               + qf[i].z*kf.z + qf[i].w*kf.w;
                }
            }
        }

        // ----- scale + causal mask (base-2 log domain) -----
        const bool need_mask = (k0 + 127 > q0);
        #pragma unroll
        for (int i = 0; i < 4; i++) {
            int q = q0 + 4*ty + i;
            #pragma unroll
            for (int j = 0; j < 8; j++) {
                float s = acc[i][j] * sscale;
                if (need_mask && (k0 + 8*tx + j > q)) s = -1e30f;
                acc[i][j] = s;
            }
        }

        // ----- online softmax update -----
        #pragma unroll
        for (int i = 0; i < 4; i++) {
            float mloc = acc[i][0];
            #pragma unroll
            for (int j = 1; j < 8; j++) mloc = fmaxf(mloc, acc[i][j]);
            #pragma unroll
            for (int off = 8; off >= 1; off >>= 1)
                mloc = fmaxf(mloc, __shfl_xor_sync(0xffffffffu, mloc, off));
            float mn = fmaxf(m_st[i], mloc);
            float corr = exp2f(m_st[i] - mn);
            m_st[i] = mn;
            float rs = 0.f;
            #pragma unroll
            for (int j = 0; j < 8; j++) {
                acc[i][j] = exp2f(acc[i][j] - mn);
                rs += acc[i][j];
            }
            #pragma unroll
            for (int off = 8; off >= 1; off >>= 1)
                rs += __shfl_xor_sync(0xffffffffu, rs, off);
            l_st[i] = l_st[i] * corr + rs;
            #pragma unroll
            for (int j = 0; j < 4; j++) o[i][j] *= corr;
        }

        __syncthreads();   // everyone done reading Ks -> safe to write Ps

        // write P[64][128] (pitch 128), rows 4ty+i, cols 8tx..8tx+7
        #pragma unroll
        for (int i = 0; i < 4; i++) {
            *(float4*)&Ps[(4*ty + i)*128 + 8*tx] =
                make_float4(acc[i][0], acc[i][1], acc[i][2], acc[i][3]);
            *(float4*)&Ps[(4*ty + i)*128 + 8*tx + 4] =
                make_float4(acc[i][4], acc[i][5], acc[i][6], acc[i][7]);
        }
        __syncthreads();

        // ----- O += P V : contract over 128 keys, unroll 4 -----
        #pragma unroll 8
        for (int kk = 0; kk < 128; kk += 4) {
            float4 pf[4];
            #pragma unroll
            for (int i = 0; i < 4; i++)
                pf[i] = *(float4*)&Ps[(4*ty + i)*128 + kk];   // broadcast
            float4 v0 = *(float4*)&Vs[(kk + 0)*64 + 4*tx];
            float4 v1 = *(float4*)&Vs[(kk + 1)*64 + 4*tx];
            float4 v2 = *(float4*)&Vs[(kk + 2)*64 + 4*tx];
            float4 v3 = *(float4*)&Vs[(kk + 3)*64 + 4*tx];
            #pragma unroll
            for (int i = 0; i < 4; i++) {
                float4 p = pf[i];
                o[i][0] += p.x*v0.x + p.y*v1.x + p.z*v2.x + p.w*v3.x;
                o[i][1] += p.x*v0.y + p.y*v1.y + p.z*v2.y + p.w*v3.y;
                o[i][2] += p.x*v0.z + p.y*v1.z + p.z*v2.z + p.w*v3.z;
                o[i][3] += p.x*v0.w + p.y*v1.w + p.z*v2.w + p.w*v3.w;
            }
        }
    }

    // epilogue: normalize and store
    #pragma unroll
    for (int i = 0; i < 4; i++) {
        float inv = 1.f / l_st[i];
        float4 r = make_float4(o[i][0]*inv, o[i][1]*inv, o[i][2]*inv, o[i][3]*inv);
        *(float4*)&out[((size_t)b * SEQ + q0 + 4*ty + i) * HEAD + 4*tx] = r;
    }
}

// ---------------------------------------------------------------------------
extern "C" void kernel_launch(void* const* d_in, const int* in_sizes, int n_in,
                              void* d_out, int out_size)
{
    const float* X  = (const float*)d_in[0];
    const float* Wq = (const float*)d_in[1];
    const float* Wk = (const float*)d_in[2];
    const float* Wv = (const float*)d_in[3];
    float* out = (float*)d_out;

    // 80 KB dynamic shared for the attention kernel
    static const int ATTN_SMEM = 20480 * (int)sizeof(float);
    cudaFuncSetAttribute(attn_kernel,
                         cudaFuncAttributeMaxDynamicSharedMemorySize, ATTN_SMEM);

    dim3 g1(3, NTOK / 128);
    qkv_kernel<<<g1, 256>>>(X, Wq, Wk, Wv);

    dim3 g2(SEQ / 64, BATCH);
    attn_kernel<<<g2, 256, ATTN_SMEM>>>(out);
}

// round 2
// speedup vs baseline: 1.2916x; 1.2916x over previous
#include <cuda_runtime.h>

#define BATCH 8
#define SEQ   2048
#define EMB   1024
#define HEAD  64
#define NTOK  (BATCH*SEQ)   // 16384
#define LOG2E 1.4426950408889634f

typedef unsigned long long u64;

// packed f32x2 helpers (Blackwell FFMA2 — ptxas never emits these from C++)
__device__ __forceinline__ u64 ffma2(u64 a, u64 b, u64 c) {
    u64 d; asm("fma.rn.f32x2 %0, %1, %2, %3;" : "=l"(d) : "l"(a), "l"(b), "l"(c));
    return d;
}
__device__ __forceinline__ u64 fmul2(u64 a, u64 b) {
    u64 d; asm("mul.rn.f32x2 %0, %1, %2;" : "=l"(d) : "l"(a), "l"(b));
    return d;
}
__device__ __forceinline__ float2 unpack2(u64 a) {
    float2 f; asm("mov.b64 {%0, %1}, %2;" : "=f"(f.x), "=f"(f.y) : "l"(a));
    return f;
}
__device__ __forceinline__ u64 pack2(float lo, float hi) {
    u64 d; asm("mov.b64 %0, {%1, %2};" : "=l"(d) : "f"(lo), "f"(hi));
    return d;
}

// scratch for Q, K, V projections (4 MB each)
__device__ float g_Q[NTOK*HEAD];
__device__ float g_K[NTOK*HEAD];
__device__ float g_V[NTOK*HEAD];

// ---------------------------------------------------------------------------
// Kernel 1: QKV projection with packed f32x2 FMA.
// Out[m][n] = sum_k X[m][k]*W[k][n].  M=16384, K=1024, N=64.
// Block: 64 rows, all 64 cols, loops over the 3 weight matrices internally.
// Packing is along k: acc lane0 accumulates even k, lane1 odd k; horizontal
// sum once at the end.  X pairs are adjacent in Xs rows; W pairs are adjacent
// in a transposed tile Wt[n][k] (pitch 34 -> conflict-free b64 reads with
// column assignment n = tx + 16*j).
// grid = 256, block = 256 -> one balanced wave at 2 CTAs/SM.
// ---------------------------------------------------------------------------
__global__ __launch_bounds__(256, 2) void qkv_kernel(
    const float* __restrict__ X,
    const float* __restrict__ Wq,
    const float* __restrict__ Wk,
    const float* __restrict__ Wv)
{
    __shared__ float Xs[64*32];    // [m][k] natural, pitch 32
    __shared__ float Wt[64*34];    // [n][k] transposed, pitch 34

    const int tid = threadIdx.x;
    const int tx = tid & 15;       // col group: cols tx + 16*j
    const int ty = tid >> 4;       // rows 4*ty + i
    const int m0 = blockIdx.x * 64;

    #pragma unroll 1
    for (int w = 0; w < 3; w++) {
        const float* W  = (w == 0) ? Wq  : (w == 1) ? Wk  : Wv;
        float*       Out = (w == 0) ? g_Q : (w == 1) ? g_K : g_V;

        u64 acc[4][4];
        #pragma unroll
        for (int i = 0; i < 4; i++)
            #pragma unroll
            for (int j = 0; j < 4; j++) acc[i][j] = 0ull;

        for (int kt = 0; kt < EMB; kt += 32) {
            __syncthreads();
            // X tile 64x32: 512 float4, 2 per thread (coalesced)
            #pragma unroll
            for (int it = 0; it < 2; it++) {
                int f = tid + it * 256;
                int c = f & 7, r = f >> 3;
                *(float4*)&Xs[r*32 + 4*c] =
                    *(const float4*)&X[(size_t)(m0 + r) * EMB + kt + 4*c];
            }
            // W tile 32x64 -> transposed store into Wt[n][k]
            #pragma unroll
            for (int it = 0; it < 2; it++) {
                int f = tid + it * 256;
                int c = f & 15, r = f >> 4;       // r = k row 0..31
                float4 wv = *(const float4*)&W[(size_t)(kt + r) * HEAD + 4*c];
                Wt[(4*c + 0)*34 + r] = wv.x;
                Wt[(4*c + 1)*34 + r] = wv.y;
                Wt[(4*c + 2)*34 + r] = wv.z;
                Wt[(4*c + 3)*34 + r] = wv.w;
            }
            __syncthreads();

            #pragma unroll
            for (int kp = 0; kp < 16; kp++) {     // 16 k-pairs
                u64 xp[4], wp[4];
                #pragma unroll
                for (int i = 0; i < 4; i++)
                    xp[i] = *(const u64*)&Xs[(4*ty + i)*32 + 2*kp];
                #pragma unroll
                for (int j = 0; j < 4; j++)
                    wp[j] = *(const u64*)&Wt[(tx + 16*j)*34 + 2*kp];
                #pragma unroll
                for (int i = 0; i < 4; i++)
                    #pragma unroll
                    for (int j = 0; j < 4; j++)
                        acc[i][j] = ffma2(xp[i], wp[j], acc[i][j]);
            }
        }
        __syncthreads();   // done reading tiles before next w overwrites

        #pragma unroll
        for (int i = 0; i < 4; i++)
            #pragma unroll
            for (int j = 0; j < 4; j++) {
                float2 f = unpack2(acc[i][j]);
                Out[(size_t)(m0 + 4*ty + i) * HEAD + tx + 16*j] = f.x + f.y;
            }
    }
}

// ---------------------------------------------------------------------------
// Kernel 2: flash attention, packed f32x2, causal-balanced scheduling.
// Each CTA processes the q-block pair {p, 31-p} (64 queries each) -> exactly
// 17 key-tiles of work per CTA.  grid = (16, 8) = 128 CTAs, 256 threads.
//
// QK^T packs along head dim h (pairs adjacent in Qs rows and swizzled Ks
// rows); horizontal sum before softmax.  PV packs along key dim kk (pairs
// adjacent in Ps rows and in transposed Vt[j][kk], pitch 130); horizontal
// sum at the epilogue.
// Shared: Qs[64][64] | Ks[128][64] swizzled (aliased with Ps[64][128]) |
//         Vt[64][130]
// ---------------------------------------------------------------------------
__global__ __launch_bounds__(256, 1) void attn_kernel(float* __restrict__ out)
{
    extern __shared__ float smem[];
    float* Qs = smem;            // 4096 floats
    float* Ks = smem + 4096;     // 8192 floats (aliased with Ps)
    float* Ps = Ks;              // P[64][128]
    float* Vt = smem + 12288;    // 64 x 130 = 8320 floats

    const int tid = threadIdx.x;
    const int tx = tid & 15;
    const int ty = tid >> 4;
    const int b  = blockIdx.y;

    const float* Qg = g_Q + (size_t)b * SEQ * HEAD;
    const float* Kg = g_K + (size_t)b * SEQ * HEAD;
    const float* Vg = g_V + (size_t)b * SEQ * HEAD;
    const float sscale = 0.03125f * LOG2E;   // C^-0.5 * log2(e)

    #pragma unroll 1
    for (int half = 0; half < 2; half++) {
        const int qb = half ? (31 - blockIdx.x) : blockIdx.x;
        const int q0 = qb * 64;

        // load Q tile 64x64 (natural; safe: no other thread reads Qs here)
        #pragma unroll
        for (int it = 0; it < 4; it++) {
            int f = tid + it * 256;
            int c = f & 15, r = f >> 4;
            *(float4*)&Qs[r*64 + 4*c] =
                *(const float4*)&Qg[(size_t)(q0 + r) * HEAD + 4*c];
        }

        float m_st[4], l_st[4];
        u64 o2[4][4];
        #pragma unroll
        for (int i = 0; i < 4; i++) {
            m_st[i] = -1e30f; l_st[i] = 0.f;
            #pragma unroll
            for (int j = 0; j < 4; j++) o2[i][j] = 0ull;
        }

        const int ntiles = q0 / 128 + 1;

        for (int kt = 0; kt < ntiles; kt++) {
            const int k0 = kt * 128;
            __syncthreads();   // prior PV done with Ps/Vt; Q visible

            // K fill (16B-chunk XOR swizzle) + V fill (transposed, pitch 130)
            #pragma unroll
            for (int it = 0; it < 8; it++) {
                int f = tid + it * 256;
                int c = f & 15, r = f >> 4;     // r 0..127
                float4 kv = *(const float4*)&Kg[(size_t)(k0 + r) * HEAD + 4*c];
                int cs = c ^ ((r >> 3) & 15);
                *(float4*)&Ks[r*64 + 4*cs] = kv;
                float4 vv = *(const float4*)&Vg[(size_t)(k0 + r) * HEAD + 4*c];
                Vt[(4*c + 0)*130 + r] = vv.x;
                Vt[(4*c + 1)*130 + r] = vv.y;
                Vt[(4*c + 2)*130 + r] = vv.z;
                Vt[(4*c + 3)*130 + r] = vv.w;
            }
            __syncthreads();

            // ----- S = Q K^T packed along h -----
            u64 s2[4][8];
            #pragma unroll
            for (int i = 0; i < 4; i++)
                #pragma unroll
                for (int j = 0; j < 8; j++) s2[i][j] = 0ull;

            #pragma unroll 4
            for (int hp = 0; hp < 32; hp++) {
                u64 qp[4];
                #pragma unroll
                for (int i = 0; i < 4; i++)
                    qp[i] = *(const u64*)&Qs[(4*ty + i)*64 + 2*hp];
                const int swz = 4*((hp >> 1) ^ tx) + 2*(hp & 1);
                #pragma unroll
                for (int jj = 0; jj < 8; jj++) {
                    u64 kp = *(const u64*)&Ks[(8*tx + jj)*64 + swz];
                    #pragma unroll
                    for (int i = 0; i < 4; i++)
                        s2[i][jj] = ffma2(qp[i], kp, s2[i][jj]);
                }
            }

            // ----- horizontal sum, scale, causal mask -----
            float s[4][8];
            const bool need_mask = (k0 + 127 > q0);
            #pragma unroll
            for (int i = 0; i < 4; i++) {
                int q = q0 + 4*ty + i;
                #pragma unroll
                for (int jj = 0; jj < 8; jj++) {
                    float2 f = unpack2(s2[i][jj]);
                    float v = (f.x + f.y) * sscale;
                    if (need_mask && (k0 + 8*tx + jj > q)) v = -1e30f;
                    s[i][jj] = v;
                }
            }

            // ----- online softmax update -----
            #pragma unroll
            for (int i = 0; i < 4; i++) {
                float mloc = s[i][0];
                #pragma unroll
                for (int jj = 1; jj < 8; jj++) mloc = fmaxf(mloc, s[i][jj]);
                #pragma unroll
                for (int off = 8; off >= 1; off >>= 1)
                    mloc = fmaxf(mloc, __shfl_xor_sync(0xffffffffu, mloc, off));
                float mn = fmaxf(m_st[i], mloc);
                float corr = exp2f(m_st[i] - mn);
                m_st[i] = mn;
                float rs = 0.f;
                #pragma unroll
                for (int jj = 0; jj < 8; jj++) {
                    s[i][jj] = exp2f(s[i][jj] - mn);
                    rs += s[i][jj];
                }
                #pragma unroll
                for (int off = 8; off >= 1; off >>= 1)
                    rs += __shfl_xor_sync(0xffffffffu, rs, off);
                l_st[i] = l_st[i] * corr + rs;
                u64 corr2 = pack2(corr, corr);
                #pragma unroll
                for (int j = 0; j < 4; j++) o2[i][j] = fmul2(o2[i][j], corr2);
            }

            __syncthreads();   // all done reading Ks -> safe to write Ps

            #pragma unroll
            for (int i = 0; i < 4; i++) {
                *(float4*)&Ps[(4*ty + i)*128 + 8*tx] =
                    make_float4(s[i][0], s[i][1], s[i][2], s[i][3]);
                *(float4*)&Ps[(4*ty + i)*128 + 8*tx + 4] =
                    make_float4(s[i][4], s[i][5], s[i][6], s[i][7]);
            }
            __syncthreads();

            // ----- O += P V packed along kk -----
            #pragma unroll 4
            for (int kkp = 0; kkp < 64; kkp++) {
                u64 p2[4], v2[4];
                #pragma unroll
                for (int i = 0; i < 4; i++)
                    p2[i] = *(const u64*)&Ps[(4*ty + i)*128 + 2*kkp];
                #pragma unroll
                for (int j = 0; j < 4; j++)
                    v2[j] = *(const u64*)&Vt[(tx + 16*j)*130 + 2*kkp];
                #pragma unroll
                for (int i = 0; i < 4; i++)
                    #pragma unroll
                    for (int j = 0; j < 4; j++)
                        o2[i][j] = ffma2(p2[i], v2[j], o2[i][j]);
            }
        }

        // epilogue: horizontal sum, normalize, store
        #pragma unroll
        for (int i = 0; i < 4; i++) {
            float inv = 1.f / l_st[i];
            #pragma unroll
            for (int j = 0; j < 4; j++) {
                float2 f = unpack2(o2[i][j]);
                out[((size_t)b * SEQ + q0 + 4*ty + i) * HEAD + tx + 16*j] =
                    (f.x + f.y) * inv;
            }
        }
        __syncthreads();   // epilogue reads done before next half refills smem
    }
}

// ---------------------------------------------------------------------------
extern "C" void kernel_launch(void* const* d_in, const int* in_sizes, int n_in,
                              void* d_out, int out_size)
{
    const float* X  = (const float*)d_in[0];
    const float* Wq = (const float*)d_in[1];
    const float* Wk = (const float*)d_in[2];
    const float* Wv = (const float*)d_in[3];
    float* out = (float*)d_out;

    static const int ATTN_SMEM = 20608 * (int)sizeof(float);   // 82432 B
    cudaFuncSetAttribute(attn_kernel,
                         cudaFuncAttributeMaxDynamicSharedMemorySize, ATTN_SMEM);

    qkv_kernel<<<NTOK / 64, 256>>>(X, Wq, Wk, Wv);

    dim3 g2(16, BATCH);
    attn_kernel<<<g2, 256, ATTN_SMEM>>>(out);
}

// round 4
// speedup vs baseline: 2.0259x; 1.5685x over previous
#include <cuda_runtime.h>
#include <cstdint>

#define BATCH 8
#define SEQ   2048
#define EMB   1024
#define HEAD  64
#define NTOK  (BATCH*SEQ)   // 16384
#define LOG2E 1.4426950408889634f

typedef unsigned long long u64;

// ---------------------------------------------------------------------------
// PTX helpers (family-portable only — no tcgen05 on this build's PTX target)
// ---------------------------------------------------------------------------
__device__ __forceinline__ u64 ffma2(u64 a, u64 b, u64 c) {
    u64 d; asm("fma.rn.f32x2 %0, %1, %2, %3;" : "=l"(d) : "l"(a), "l"(b), "l"(c));
    return d;
}
__device__ __forceinline__ u64 fmul2(u64 a, u64 b) {
    u64 d; asm("mul.rn.f32x2 %0, %1, %2;" : "=l"(d) : "l"(a), "l"(b));
    return d;
}
__device__ __forceinline__ float2 unpack2(u64 a) {
    float2 f; asm("mov.b64 {%0, %1}, %2;" : "=f"(f.x), "=f"(f.y) : "l"(a));
    return f;
}
__device__ __forceinline__ u64 pack2(float lo, float hi) {
    u64 d; asm("mov.b64 %0, {%1, %2};" : "=l"(d) : "f"(lo), "f"(hi));
    return d;
}
__device__ __forceinline__ float tf32r(float x) {
    float y; asm("cvt.rna.tf32.f32 %0, %1;" : "=f"(y) : "f"(x)); return y;
}

// m16n8k8 tf32 mma.sync (sm_80+, family-portable)
__device__ __forceinline__ void mma_tf32(float* d, const uint32_t* a, const uint32_t* b) {
    asm volatile(
        "mma.sync.aligned.m16n8k8.row.col.f32.tf32.tf32.f32 "
        "{%0,%1,%2,%3}, {%4,%5,%6,%7}, {%8,%9}, {%0,%1,%2,%3};"
        : "+f"(d[0]), "+f"(d[1]), "+f"(d[2]), "+f"(d[3])
        : "r"(a[0]), "r"(a[1]), "r"(a[2]), "r"(a[3]), "r"(b[0]), "r"(b[1]));
}

// ---------------------------------------------------------------------------
// device scratch
// ---------------------------------------------------------------------------
__device__ float g_Q[NTOK*HEAD];
__device__ float g_K[NTOK*HEAD];
__device__ float g_V[NTOK*HEAD];

// ---------------------------------------------------------------------------
// Kernel 1: QKV projection via mma.sync tf32.
// Out[m][n] = sum_k X[m][k]*W[k][n].  M=16384, K=1024, N=64 (x3 matrices).
// grid = 128 (M tiles of 128), 256 threads = 8 warps (4 m-warps x 2 n-warps),
// warp tile 32x32 = 2x4 m16n8k8 frags; 3 accumulator sets (Q,K,V) held in
// registers so the X tile is staged once per K-tile of 32.
// Smem: XsT[k][m] pitch 132 and Ws[k][n] pitch 68 -> fragment LDS bank =
// (4c + r) mod 32, conflict-free.
// ---------------------------------------------------------------------------
__global__ __launch_bounds__(256, 1) void qkv_mma(
    const float* __restrict__ X,
    const float* __restrict__ Wq,
    const float* __restrict__ Wk,
    const float* __restrict__ Wv)
{
    __shared__ float XsT[32][132];    // [k][m] transposed
    __shared__ float Ws[3][32][68];   // [w][k][n] natural

    const int tid  = threadIdx.x;
    const int wid  = tid >> 5;
    const int lane = tid & 31;
    const int mw   = wid >> 1;        // 0..3
    const int nw   = wid & 1;         // 0..1
    const int m0   = blockIdx.x * 128;

    const int r = lane >> 2;          // 0..7  (group id)
    const int c = lane & 3;           // 0..3  (thread in group)

    const float* Wsrc[3] = { Wq, Wk, Wv };

    float acc[3][2][4][4];
    #pragma unroll
    for (int w = 0; w < 3; w++)
        #pragma unroll
        for (int mf = 0; mf < 2; mf++)
            #pragma unroll
            for (int nf = 0; nf < 4; nf++)
                #pragma unroll
                for (int e = 0; e < 4; e++) acc[w][mf][nf][e] = 0.f;

    for (int kt = 0; kt < 32; kt++) {
        __syncthreads();
        // X tile 128x32 -> XsT transposed (1024 f4, 4/thread), tf32-rounded
        #pragma unroll
        for (int it = 0; it < 4; it++) {
            int f = tid + it * 256;
            int cc = f & 7, rr = f >> 3;   // cc = k group, rr = m row
            float4 v = *(const float4*)&X[(size_t)(m0 + rr) * EMB + kt*32 + 4*cc];
            XsT[4*cc + 0][rr] = tf32r(v.x);
            XsT[4*cc + 1][rr] = tf32r(v.y);
            XsT[4*cc + 2][rr] = tf32r(v.z);
            XsT[4*cc + 3][rr] = tf32r(v.w);
        }
        // W tiles: 3 x 32x64 (1536 f4, 6/thread), natural layout
        #pragma unroll
        for (int it = 0; it < 6; it++) {
            int f = tid + it * 256;
            int w = f >> 9;
            int rem = f & 511;
            int cc = rem & 15, rr = rem >> 4;   // cc = n group, rr = k row
            float4 v = *(const float4*)&Wsrc[w][(size_t)(kt*32 + rr) * HEAD + 4*cc];
            v.x = tf32r(v.x); v.y = tf32r(v.y); v.z = tf32r(v.z); v.w = tf32r(v.w);
            *(float4*)&Ws[w][rr][4*cc] = v;
        }
        __syncthreads();

        #pragma unroll
        for (int ks = 0; ks < 4; ks++) {
            const int k = ks * 8;
            uint32_t a[2][4];
            #pragma unroll
            for (int mf = 0; mf < 2; mf++) {
                const int m = mw*32 + mf*16;
                a[mf][0] = __float_as_uint(XsT[k + c    ][m + r    ]);
                a[mf][1] = __float_as_uint(XsT[k + c    ][m + r + 8]);
                a[mf][2] = __float_as_uint(XsT[k + c + 4][m + r    ]);
                a[mf][3] = __float_as_uint(XsT[k + c + 4][m + r + 8]);
            }
            #pragma unroll
            for (int w = 0; w < 3; w++) {
                uint32_t b[4][2];
                #pragma unroll
                for (int nf = 0; nf < 4; nf++) {
                    const int n = nw*32 + nf*8;
                    b[nf][0] = __float_as_uint(Ws[w][k + c    ][n + r]);
                    b[nf][1] = __float_as_uint(Ws[w][k + c + 4][n + r]);
                }
                #pragma unroll
                for (int mf = 0; mf < 2; mf++)
                    #pragma unroll
                    for (int nf = 0; nf < 4; nf++)
                        mma_tf32(acc[w][mf][nf], a[mf], b[nf]);
            }
        }
    }

    // epilogue: C frag layout -> global.  d0,d1 = (row, 2c), (row, 2c+1);
    // d2,d3 = (row+8, ...)
    #pragma unroll
    for (int w = 0; w < 3; w++) {
        float* Out = (w == 0) ? g_Q : (w == 1) ? g_K : g_V;
        #pragma unroll
        for (int mf = 0; mf < 2; mf++) {
            const int mrow = m0 + mw*32 + mf*16 + r;
            #pragma unroll
            for (int nf = 0; nf < 4; nf++) {
                const int n = nw*32 + nf*8 + 2*c;
                *(float2*)&Out[(size_t)mrow * HEAD + n] =
                    make_float2(acc[w][mf][nf][0], acc[w][mf][nf][1]);
                *(float2*)&Out[(size_t)(mrow + 8) * HEAD + n] =
                    make_float2(acc[w][mf][nf][2], acc[w][mf][nf][3]);
            }
        }
    }
}

// ---------------------------------------------------------------------------
// Kernel 2: flash attention (unchanged — known good, 151.8us)
// ---------------------------------------------------------------------------
__global__ __launch_bounds__(256, 1) void attn_kernel(float* __restrict__ out)
{
    extern __shared__ float fsmem[];
    float* Qs = fsmem;
    float* Ks = fsmem + 4096;
    float* Ps = Ks;
    float* Vt = fsmem + 12288;

    const int tid = threadIdx.x;
    const int tx = tid & 15;
    const int ty = tid >> 4;
    const int b  = blockIdx.y;

    const float* Qg = g_Q + (size_t)b * SEQ * HEAD;
    const float* Kg = g_K + (size_t)b * SEQ * HEAD;
    const float* Vg = g_V + (size_t)b * SEQ * HEAD;
    const float sscale = 0.03125f * LOG2E;

    #pragma unroll 1
    for (int half = 0; half < 2; half++) {
        const int qb = half ? (31 - blockIdx.x) : blockIdx.x;
        const int q0 = qb * 64;

        #pragma unroll
        for (int it = 0; it < 4; it++) {
            int f = tid + it * 256;
            int c = f & 15, r = f >> 4;
            *(float4*)&Qs[r*64 + 4*c] =
                *(const float4*)&Qg[(size_t)(q0 + r) * HEAD + 4*c];
        }

        float m_st[4], l_st[4];
        u64 o2[4][4];
        #pragma unroll
        for (int i = 0; i < 4; i++) {
            m_st[i] = -1e30f; l_st[i] = 0.f;
            #pragma unroll
            for (int j = 0; j < 4; j++) o2[i][j] = 0ull;
        }

        const int ntiles = q0 / 128 + 1;

        for (int kt = 0; kt < ntiles; kt++) {
            const int k0 = kt * 128;
            __syncthreads();

            #pragma unroll
            for (int it = 0; it < 8; it++) {
                int f = tid + it * 256;
                int c = f & 15, r = f >> 4;
                float4 kv = *(const float4*)&Kg[(size_t)(k0 + r) * HEAD + 4*c];
                int cs = c ^ ((r >> 3) & 15);
                *(float4*)&Ks[r*64 + 4*cs] = kv;
                float4 vv = *(const float4*)&Vg[(size_t)(k0 + r) * HEAD + 4*c];
                Vt[(4*c + 0)*130 + r] = vv.x;
                Vt[(4*c + 1)*130 + r] = vv.y;
                Vt[(4*c + 2)*130 + r] = vv.z;
                Vt[(4*c + 3)*130 + r] = vv.w;
            }
            __syncthreads();

            u64 s2[4][8];
            #pragma unroll
            for (int i = 0; i < 4; i++)
                #pragma unroll
                for (int j = 0; j < 8; j++) s2[i][j] = 0ull;

            #pragma unroll 4
            for (int hp = 0; hp < 32; hp++) {
                u64 qp[4];
                #pragma unroll
                for (int i = 0; i < 4; i++)
                    qp[i] = *(const u64*)&Qs[(4*ty + i)*64 + 2*hp];
                const int swz = 4*((hp >> 1) ^ tx) + 2*(hp & 1);
                #pragma unroll
                for (int jj = 0; jj < 8; jj++) {
                    u64 kp = *(const u64*)&Ks[(8*tx + jj)*64 + swz];
                    #pragma unroll
                    for (int i = 0; i < 4; i++)
                        s2[i][jj] = ffma2(qp[i], kp, s2[i][jj]);
                }
            }

            float s[4][8];
            const bool need_mask = (k0 + 127 > q0);
            #pragma unroll
            for (int i = 0; i < 4; i++) {
                int q = q0 + 4*ty + i;
                #pragma unroll
                for (int jj = 0; jj < 8; jj++) {
                    float2 f = unpack2(s2[i][jj]);
                    float v = (f.x + f.y) * sscale;
                    if (need_mask && (k0 + 8*tx + jj > q)) v = -1e30f;
                    s[i][jj] = v;
                }
            }

            #pragma unroll
            for (int i = 0; i < 4; i++) {
                float mloc = s[i][0];
                #pragma unroll
                for (int jj = 1; jj < 8; jj++) mloc = fmaxf(mloc, s[i][jj]);
                #pragma unroll
                for (int off = 8; off >= 1; off >>= 1)
                    mloc = fmaxf(mloc, __shfl_xor_sync(0xffffffffu, mloc, off));
                float mn = fmaxf(m_st[i], mloc);
                float corr = exp2f(m_st[i] - mn);
                m_st[i] = mn;
                float rs = 0.f;
                #pragma unroll
                for (int jj = 0; jj < 8; jj++) {
                    s[i][jj] = exp2f(s[i][jj] - mn);
                    rs += s[i][jj];
                }
                #pragma unroll
                for (int off = 8; off >= 1; off >>= 1)
                    rs += __shfl_xor_sync(0xffffffffu, rs, off);
                l_st[i] = l_st[i] * corr + rs;
                u64 corr2 = pack2(corr, corr);
                #pragma unroll
                for (int j = 0; j < 4; j++) o2[i][j] = fmul2(o2[i][j], corr2);
            }

            __syncthreads();

            #pragma unroll
            for (int i = 0; i < 4; i++) {
                *(float4*)&Ps[(4*ty + i)*128 + 8*tx] =
                    make_float4(s[i][0], s[i][1], s[i][2], s[i][3]);
                *(float4*)&Ps[(4*ty + i)*128 + 8*tx + 4] =
                    make_float4(s[i][4], s[i][5], s[i][6], s[i][7]);
            }
            __syncthreads();

            #pragma unroll 4
            for (int kkp = 0; kkp < 64; kkp++) {
                u64 p2[4], v2[4];
                #pragma unroll
                for (int i = 0; i < 4; i++)
                    p2[i] = *(const u64*)&Ps[(4*ty + i)*128 + 2*kkp];
                #pragma unroll
                for (int j = 0; j < 4; j++)
                    v2[j] = *(const u64*)&Vt[(tx + 16*j)*130 + 2*kkp];
                #pragma unroll
                for (int i = 0; i < 4; i++)
                    #pragma unroll
                    for (int j = 0; j < 4; j++)
                        o2[i][j] = ffma2(p2[i], v2[j], o2[i][j]);
            }
        }

        #pragma unroll
        for (int i = 0; i < 4; i++) {
            float inv = 1.f / l_st[i];
            #pragma unroll
            for (int j = 0; j < 4; j++) {
                float2 f = unpack2(o2[i][j]);
                out[((size_t)b * SEQ + q0 + 4*ty + i) * HEAD + tx + 16*j] =
                    (f.x + f.y) * inv;
            }
        }
        __syncthreads();
    }
}

// ---------------------------------------------------------------------------
extern "C" void kernel_launch(void* const* d_in, const int* in_sizes, int n_in,
                              void* d_out, int out_size)
{
    const float* X  = (const float*)d_in[0];
    const float* Wq = (const float*)d_in[1];
    const float* Wk = (const float*)d_in[2];
    const float* Wv = (const float*)d_in[3];
    float* out = (float*)d_out;

    static const int ATTN_SMEM = 20608 * (int)sizeof(float);   // 82432 B
    cudaFuncSetAttribute(attn_kernel,
                         cudaFuncAttributeMaxDynamicSharedMemorySize, ATTN_SMEM);

    qkv_mma<<<NTOK / 128, 256>>>(X, Wq, Wk, Wv);

    dim3 g2(16, BATCH);
    attn_kernel<<<g2, 256, ATTN_SMEM>>>(out);
}

// round 5
// speedup vs baseline: 3.0800x; 1.5203x over previous
#include <cuda_runtime.h>
#include <cstdint>

#define BATCH 8
#define SEQ   2048
#define EMB   1024
#define HEAD  64
#define NTOK  (BATCH*SEQ)   // 16384
#define LOG2E 1.4426950408889634f

// ---------------------------------------------------------------------------
// PTX helpers (family-portable only)
// ---------------------------------------------------------------------------
__device__ __forceinline__ float tf32r(float x) {
    float y; asm("cvt.rna.tf32.f32 %0, %1;" : "=f"(y) : "f"(x)); return y;
}

// m16n8k8 tf32 mma.sync (sm_80+, family-portable; frag mapping HW-validated R4)
__device__ __forceinline__ void mma_tf32(float* d, const uint32_t* a, const uint32_t* b) {
    asm volatile(
        "mma.sync.aligned.m16n8k8.row.col.f32.tf32.tf32.f32 "
        "{%0,%1,%2,%3}, {%4,%5,%6,%7}, {%8,%9}, {%0,%1,%2,%3};"
        : "+f"(d[0]), "+f"(d[1]), "+f"(d[2]), "+f"(d[3])
        : "r"(a[0]), "r"(a[1]), "r"(a[2]), "r"(a[3]), "r"(b[0]), "r"(b[1]));
}

// ---------------------------------------------------------------------------
// device scratch
// ---------------------------------------------------------------------------
__device__ float g_Q[NTOK*HEAD];
__device__ float g_K[NTOK*HEAD];
__device__ float g_V[NTOK*HEAD];

// ---------------------------------------------------------------------------
// Kernel 1: QKV projection via mma.sync tf32 (unchanged from R4 — passed)
// ---------------------------------------------------------------------------
__global__ __launch_bounds__(256, 1) void qkv_mma(
    const float* __restrict__ X,
    const float* __restrict__ Wq,
    const float* __restrict__ Wk,
    const float* __restrict__ Wv)
{
    __shared__ float XsT[32][132];    // [k][m] transposed
    __shared__ float Ws[3][32][68];   // [w][k][n] natural

    const int tid  = threadIdx.x;
    const int wid  = tid >> 5;
    const int lane = tid & 31;
    const int mw   = wid >> 1;
    const int nw   = wid & 1;
    const int m0   = blockIdx.x * 128;

    const int r = lane >> 2;
    const int c = lane & 3;

    const float* Wsrc[3] = { Wq, Wk, Wv };

    float acc[3][2][4][4];
    #pragma unroll
    for (int w = 0; w < 3; w++)
        #pragma unroll
        for (int mf = 0; mf < 2; mf++)
            #pragma unroll
            for (int nf = 0; nf < 4; nf++)
                #pragma unroll
                for (int e = 0; e < 4; e++) acc[w][mf][nf][e] = 0.f;

    for (int kt = 0; kt < 32; kt++) {
        __syncthreads();
        #pragma unroll
        for (int it = 0; it < 4; it++) {
            int f = tid + it * 256;
            int cc = f & 7, rr = f >> 3;
            float4 v = *(const float4*)&X[(size_t)(m0 + rr) * EMB + kt*32 + 4*cc];
            XsT[4*cc + 0][rr] = tf32r(v.x);
            XsT[4*cc + 1][rr] = tf32r(v.y);
            XsT[4*cc + 2][rr] = tf32r(v.z);
            XsT[4*cc + 3][rr] = tf32r(v.w);
        }
        #pragma unroll
        for (int it = 0; it < 6; it++) {
            int f = tid + it * 256;
            int w = f >> 9;
            int rem = f & 511;
            int cc = rem & 15, rr = rem >> 4;
            float4 v = *(const float4*)&Wsrc[w][(size_t)(kt*32 + rr) * HEAD + 4*cc];
            v.x = tf32r(v.x); v.y = tf32r(v.y); v.z = tf32r(v.z); v.w = tf32r(v.w);
            *(float4*)&Ws[w][rr][4*cc] = v;
        }
        __syncthreads();

        #pragma unroll
        for (int ks = 0; ks < 4; ks++) {
            const int k = ks * 8;
            uint32_t a[2][4];
            #pragma unroll
            for (int mf = 0; mf < 2; mf++) {
                const int m = mw*32 + mf*16;
                a[mf][0] = __float_as_uint(XsT[k + c    ][m + r    ]);
                a[mf][1] = __float_as_uint(XsT[k + c    ][m + r + 8]);
                a[mf][2] = __float_as_uint(XsT[k + c + 4][m + r    ]);
                a[mf][3] = __float_as_uint(XsT[k + c + 4][m + r + 8]);
            }
            #pragma unroll
            for (int w = 0; w < 3; w++) {
                uint32_t b[4][2];
                #pragma unroll
                for (int nf = 0; nf < 4; nf++) {
                    const int n = nw*32 + nf*8;
                    b[nf][0] = __float_as_uint(Ws[w][k + c    ][n + r]);
                    b[nf][1] = __float_as_uint(Ws[w][k + c + 4][n + r]);
                }
                #pragma unroll
                for (int mf = 0; mf < 2; mf++)
                    #pragma unroll
                    for (int nf = 0; nf < 4; nf++)
                        mma_tf32(acc[w][mf][nf], a[mf], b[nf]);
            }
        }
    }

    #pragma unroll
    for (int w = 0; w < 3; w++) {
        float* Out = (w == 0) ? g_Q : (w == 1) ? g_K : g_V;
        #pragma unroll
        for (int mf = 0; mf < 2; mf++) {
            const int mrow = m0 + mw*32 + mf*16 + r;
            #pragma unroll
            for (int nf = 0; nf < 4; nf++) {
                const int n = nw*32 + nf*8 + 2*c;
                *(float2*)&Out[(size_t)mrow * HEAD + n] =
                    make_float2(acc[w][mf][nf][0], acc[w][mf][nf][1]);
                *(float2*)&Out[(size_t)(mrow + 8) * HEAD + n] =
                    make_float2(acc[w][mf][nf][2], acc[w][mf][nf][3]);
            }
        }
    }
}

// ---------------------------------------------------------------------------
// Kernel 2: flash attention via mma.sync tf32.
// q-tile 64, kv-tile 128, balanced pairs {qb, 31-qb} -> 17 tiles/CTA.
// grid (16, 8), 256 threads = 8 warps: mw = wid>>1 (16 q-rows each),
// nw = wid&1 (keys half for QK^T; head half for PV).
// smem (floats): Qs 64x68 | Ks 128x68 (alias Ps 64x132) | Vs 128x68 |
//                redmax[2][64], redsum[2][64]
// ---------------------------------------------------------------------------
#define ATTN_SMEM_FLOATS (4352 + 8704 + 8704 + 256)

__global__ __launch_bounds__(256, 1) void attn_mma(float* __restrict__ out)
{
    extern __shared__ float sm[];
    float* Qs = sm;                       // pitch 68
    float* Ks = sm + 4352;                // pitch 68
    float* Ps = Ks;                       // pitch 132 (alias)
    float* Vs = sm + 4352 + 8704;         // pitch 68
    float* redmax = sm + 4352 + 8704 + 8704;   // [2][64]
    float* redsum = redmax + 128;              // [2][64]

    const int tid  = threadIdx.x;
    const int wid  = tid >> 5;
    const int lane = tid & 31;
    const int mw   = wid >> 1;
    const int nw   = wid & 1;
    const int r    = lane >> 2;
    const int c    = lane & 3;
    const int b    = blockIdx.y;

    const float* Qg = g_Q + (size_t)b * SEQ * HEAD;
    const float* Kg = g_K + (size_t)b * SEQ * HEAD;
    const float* Vg = g_V + (size_t)b * SEQ * HEAD;
    const float qscale = 0.03125f * LOG2E;   // C^-0.5 * log2(e), folded into Q

    const int rowbase = mw*16 + r;

    #pragma unroll 1
    for (int half = 0; half < 2; half++) {
        const int qb = half ? (31 - (int)blockIdx.x) : (int)blockIdx.x;
        const int q0 = qb * 64;

        // stage Q (scaled + tf32).  Safe: no warp reads Qs at this point
        // (prior half's QK mma is behind at least two __syncthreads).
        #pragma unroll
        for (int it = 0; it < 4; it++) {
            int f = tid + it * 256;
            int cc = f & 15, rr = f >> 4;
            float4 v = *(const float4*)&Qg[(size_t)(q0 + rr) * HEAD + 4*cc];
            Qs[rr*68 + 4*cc + 0] = tf32r(v.x * qscale);
            Qs[rr*68 + 4*cc + 1] = tf32r(v.y * qscale);
            Qs[rr*68 + 4*cc + 2] = tf32r(v.z * qscale);
            Qs[rr*68 + 4*cc + 3] = tf32r(v.w * qscale);
        }

        float m_st[2] = { -1e30f, -1e30f };
        float l_st[2] = { 0.f, 0.f };
        float o[4][4];
        #pragma unroll
        for (int nf = 0; nf < 4; nf++)
            #pragma unroll
            for (int e = 0; e < 4; e++) o[nf][e] = 0.f;

        const int ntiles = q0 / 128 + 1;

        for (int kt = 0; kt < ntiles; kt++) {
            const int k0 = kt * 128;
            __syncthreads();   // prior PV done reading Ps(=Ks)/Vs; Q visible

            // stage K, V (128x64 each, tf32-rounded, natural pitch 68)
            #pragma unroll
            for (int it = 0; it < 8; it++) {
                int f = tid + it * 256;
                int cc = f & 15, rr = f >> 4;   // rr 0..127
                float4 kv = *(const float4*)&Kg[(size_t)(k0 + rr) * HEAD + 4*cc];
                Ks[rr*68 + 4*cc + 0] = tf32r(kv.x);
                Ks[rr*68 + 4*cc + 1] = tf32r(kv.y);
                Ks[rr*68 + 4*cc + 2] = tf32r(kv.z);
                Ks[rr*68 + 4*cc + 3] = tf32r(kv.w);
                float4 vv = *(const float4*)&Vg[(size_t)(k0 + rr) * HEAD + 4*cc];
                Vs[rr*68 + 4*cc + 0] = tf32r(vv.x);
                Vs[rr*68 + 4*cc + 1] = tf32r(vv.y);
                Vs[rr*68 + 4*cc + 2] = tf32r(vv.z);
                Vs[rr*68 + 4*cc + 3] = tf32r(vv.w);
            }
            __syncthreads();

            // ----- S = Q K^T : warp tile 16q x 64keys, 8 n-frags, 8 k-steps
            float s[8][4];
            #pragma unroll
            for (int nf = 0; nf < 8; nf++)
                #pragma unroll
                for (int e = 0; e < 4; e++) s[nf][e] = 0.f;

            #pragma unroll
            for (int ks = 0; ks < 8; ks++) {
                const int k = ks * 8;
                uint32_t a[4];
                a[0] = __float_as_uint(Qs[(mw*16 + r    )*68 + k + c    ]);
                a[1] = __float_as_uint(Qs[(mw*16 + r + 8)*68 + k + c    ]);
                a[2] = __float_as_uint(Qs[(mw*16 + r    )*68 + k + c + 4]);
                a[3] = __float_as_uint(Qs[(mw*16 + r + 8)*68 + k + c + 4]);
                #pragma unroll
                for (int nf = 0; nf < 8; nf++) {
                    const int n = nw*64 + nf*8;
                    uint32_t bb[2];
                    bb[0] = __float_as_uint(Ks[(n + r)*68 + k + c    ]);
                    bb[1] = __float_as_uint(Ks[(n + r)*68 + k + c + 4]);
                    mma_tf32(s[nf], a, bb);
                }
            }

            // ----- causal mask (scale already folded into Q) -----
            const int row0 = q0 + mw*16 + r;
            const int row1 = row0 + 8;
            if (k0 + 127 > q0) {               // only the last tile masks
                #pragma unroll
                for (int nf = 0; nf < 8; nf++) {
                    const int col = k0 + nw*64 + nf*8 + 2*c;
                    if (col     > row0) s[nf][0] = -1e30f;
                    if (col + 1 > row0) s[nf][1] = -1e30f;
                    if (col     > row1) s[nf][2] = -1e30f;
                    if (col + 1 > row1) s[nf][3] = -1e30f;
                }
            }

            // ----- row max: intra-warp over c, cross-warp (nw) via smem ----
            float pm0 = s[0][0], pm1 = s[0][2];
            #pragma unroll
            for (int nf = 0; nf < 8; nf++) {
                pm0 = fmaxf(pm0, fmaxf(s[nf][0], s[nf][1]));
                pm1 = fmaxf(pm1, fmaxf(s[nf][2], s[nf][3]));
            }
            #pragma unroll
            for (int off = 1; off <= 2; off <<= 1) {
                pm0 = fmaxf(pm0, __shfl_xor_sync(0xffffffffu, pm0, off));
                pm1 = fmaxf(pm1, __shfl_xor_sync(0xffffffffu, pm1, off));
            }
            if (c == 0) {
                redmax[nw*64 + rowbase    ] = pm0;
                redmax[nw*64 + rowbase + 8] = pm1;
            }
            __syncthreads();   // (A) also: all QK mma reads of Ks complete

            float tm0 = fmaxf(redmax[rowbase    ], redmax[64 + rowbase    ]);
            float tm1 = fmaxf(redmax[rowbase + 8], redmax[64 + rowbase + 8]);
            float mn0 = fmaxf(m_st[0], tm0);
            float mn1 = fmaxf(m_st[1], tm1);
            float corr0 = exp2f(m_st[0] - mn0);
            float corr1 = exp2f(m_st[1] - mn1);
            m_st[0] = mn0; m_st[1] = mn1;

            // p = exp2(s - mn); write P (tf32) into Ps (alias Ks — safe after A)
            float rs0 = 0.f, rs1 = 0.f;
            #pragma unroll
            for (int nf = 0; nf < 8; nf++) {
                float p0 = exp2f(s[nf][0] - mn0);
                float p1 = exp2f(s[nf][1] - mn0);
                float p2 = exp2f(s[nf][2] - mn1);
                float p3 = exp2f(s[nf][3] - mn1);
                rs0 += p0 + p1;
                rs1 += p2 + p3;
                const int col = nw*64 + nf*8 + 2*c;
                *(float2*)&Ps[(rowbase    )*132 + col] =
                    make_float2(tf32r(p0), tf32r(p1));
                *(float2*)&Ps[(rowbase + 8)*132 + col] =
                    make_float2(tf32r(p2), tf32r(p3));
            }
            #pragma unroll
            for (int off = 1; off <= 2; off <<= 1) {
                rs0 += __shfl_xor_sync(0xffffffffu, rs0, off);
                rs1 += __shfl_xor_sync(0xffffffffu, rs1, off);
            }
            if (c == 0) {
                redsum[nw*64 + rowbase    ] = rs0;
                redsum[nw*64 + rowbase + 8] = rs1;
            }
            __syncthreads();   // (B) P + redsum visible

            l_st[0] = l_st[0] * corr0 + redsum[rowbase    ] + redsum[64 + rowbase    ];
            l_st[1] = l_st[1] * corr1 + redsum[rowbase + 8] + redsum[64 + rowbase + 8];

            // O *= corr (rows r -> d0,d1 ; r+8 -> d2,d3)
            #pragma unroll
            for (int nf = 0; nf < 4; nf++) {
                o[nf][0] *= corr0; o[nf][1] *= corr0;
                o[nf][2] *= corr1; o[nf][3] *= corr1;
            }

            // ----- O += P V : warp tile 16q x 32head, 4 n-frags, 16 k-steps
            #pragma unroll
            for (int ks = 0; ks < 16; ks++) {
                const int k = ks * 8;
                uint32_t a[4];
                a[0] = __float_as_uint(Ps[(mw*16 + r    )*132 + k + c    ]);
                a[1] = __float_as_uint(Ps[(mw*16 + r + 8)*132 + k + c    ]);
                a[2] = __float_as_uint(Ps[(mw*16 + r    )*132 + k + c + 4]);
                a[3] = __float_as_uint(Ps[(mw*16 + r + 8)*132 + k + c + 4]);
                #pragma unroll
                for (int nf = 0; nf < 4; nf++) {
                    const int n = nw*32 + nf*8;
                    uint32_t bb[2];
                    bb[0] = __float_as_uint(Vs[(k + c    )*68 + n + r]);
                    bb[1] = __float_as_uint(Vs[(k + c + 4)*68 + n + r]);
                    mma_tf32(o[nf], a, bb);
                }
            }
        }

        // epilogue: normalize, store
        const int row0 = q0 + mw*16 + r;
        const float inv0 = 1.f / l_st[0];
        const float inv1 = 1.f / l_st[1];
        #pragma unroll
        for (int nf = 0; nf < 4; nf++) {
            const int n = nw*32 + nf*8 + 2*c;
            *(float2*)&out[((size_t)b * SEQ + row0) * HEAD + n] =
                make_float2(o[nf][0] * inv0, o[nf][1] * inv0);
            *(float2*)&out[((size_t)b * SEQ + row0 + 8) * HEAD + n] =
                make_float2(o[nf][2] * inv1, o[nf][3] * inv1);
        }
        __syncthreads();   // all reads done before next half restages smem
    }
}

// ---------------------------------------------------------------------------
extern "C" void kernel_launch(void* const* d_in, const int* in_sizes, int n_in,
                              void* d_out, int out_size)
{
    const float* X  = (const float*)d_in[0];
    const float* Wq = (const float*)d_in[1];
    const float* Wk = (const float*)d_in[2];
    const float* Wv = (const float*)d_in[3];
    float* out = (float*)d_out;

    static const int ATTN_SMEM = ATTN_SMEM_FLOATS * (int)sizeof(float); // 88064 B
    cudaFuncSetAttribute(attn_mma,
                         cudaFuncAttributeMaxDynamicSharedMemorySize, ATTN_SMEM);

    qkv_mma<<<NTOK / 128, 256>>>(X, Wq, Wk, Wv);

    dim3 g2(16, BATCH);
    attn_mma<<<g2, 256, ATTN_SMEM>>>(out);
}